// round 15
// baseline (speedup 1.0000x reference)
#include <cuda_runtime.h>

// RasterizePointsXYsBlending — flat scatter + smem-staged wide composite.
// B=2, P=2048, C=64, SIZE=128, K=8, RADIUS=1.5px, RAD_POW=2, TAU=1.
//
//  K1 prep (384 blocks x 256 thr):  [R12/R14-verbatim]
//     blocks [0,128):  transpose src [B,C,P] -> srcT [B,P,C]; 2 tiles per
//                      block, 2 independent LDG.128 per thread (MLP=8).
//     blocks [128,384): scatter — one thread per (point, 4x4 bbox cell):
//                      <=1 exact inside-test, <=1 atomic append (depth-1 chain).
//  K2 composite (1024 blocks x (32,8)) — R14 + doubled warp pool:
//     8 channel-group warps per 32-pixel group (8 channels/thread,
//     ~56 resident warps/SM). Block's 32 pixel-lists (slots 0..7) staged
//     to smem with 1 coalesced LDG.128/thread in parallel with the counter
//     load; one __syncthreads doubles as the read-before-clear fence.
//     cnt<=8: order-independent weights w_i = a_i*prod_{z_j<z_i}(1-a_j);
//     cnt>8 cold path reads the full global list (top-8 insertion).

#define BN 2
#define PN 2048
#define CN 64
#define SZ 128
#define KN 8
#define BIGF 1e10f
// r_ndc = 1.5/128*2 = 3*2^-7 ; r2 = 9*2^-14 (exact fp32)
#define R2 0.00054931640625f

#define CAPP 16                       // per-pixel list capacity (mean ~0.9)
#define NPIX (BN * SZ * SZ)           // 32768
#define TRB 128                       // transpose blocks (2 tiles each)
#define SCB 256                       // scatter blocks (256*256 = BN*PN*16)

__device__ float  d_srcT[BN * PN * CN];   // src transposed to [b,p,c]
__device__ int    d_cnt[NPIX];            // per-pixel counts (invariant: 0)
__device__ float4 d_list[NPIX * CAPP];    // (z, alpha, bitcast idx, -)

// ---------------------------------------------------------------- kernel 1
__global__ __launch_bounds__(256)
void prep_kernel(const float* __restrict__ src, const float* __restrict__ pts)
{
    if (blockIdx.x < TRB) {
        // -------- transpose: 2 tiles/block, 2 independent LDG.128/thread --
        __shared__ float t[2][32][33];
        const int i  = threadIdx.x;
        const int y  = i >> 3;            // 0..31 (channel row in tile)
        const int xq = (i & 7) * 4;       // 0,4,...,28 (p quad)

        float4 v[2];
#pragma unroll
        for (int q = 0; q < 2; ++q) {
            const int tl = blockIdx.x + q * TRB;     // covers 256 tiles
            const int b  = tl >> 7;
            const int c0 = ((tl >> 6) & 1) * 32;
            const int p0 = (tl & 63) * 32;
            v[q] = *(const float4*)
                (src + ((size_t)(b * CN + c0 + y) << 11) + p0 + xq);
        }
#pragma unroll
        for (int q = 0; q < 2; ++q) {
            t[q][y][xq + 0] = v[q].x;
            t[q][y][xq + 1] = v[q].y;
            t[q][y][xq + 2] = v[q].z;
            t[q][y][xq + 3] = v[q].w;
        }
        __syncthreads();

        const int c  = i & 31;            // output lane = channel
        const int pq = i >> 5;            // 0..7 (p row group of 4)
#pragma unroll
        for (int q = 0; q < 2; ++q) {
            const int tl = blockIdx.x + q * TRB;
            const int b  = tl >> 7;
            const int c0 = ((tl >> 6) & 1) * 32;
            const int p0 = (tl & 63) * 32;
#pragma unroll
            for (int r = 0; r < 4; ++r) {
                const int p = pq * 4 + r;
                d_srcT[((size_t)(b * PN + p0 + p) << 6) + c0 + c] =
                    t[q][c][p];
            }
        }
    } else {
        // ------- scatter: one thread per (point, 4x4 bbox cell) ----------
        const int s = (blockIdx.x - TRB) * 256 + threadIdx.x;
        const int cell = s & 15;
        const int rx   = cell & 3;
        const int ry   = cell >> 2;
        const int gp   = s >> 4;               // global point id
        const int b    = gp >> 11;
        const int p    = gp & (PN - 1);

        const float px = -pts[gp * 3 + 0];     // sign flip from forward
        const float py = -pts[gp * 3 + 1];
        const float pz =  pts[gp * 3 + 2];

        // pixel coords of the point: ndc(i) = 1-(2i+1)/128
        const float u = (1.0f - px) * 64.0f - 0.5f;   // w
        const float v = (1.0f - py) * 64.0f - 0.5f;   // h

        // radius 1.5 px + fp margin; bbox spans <=4 cells per axis
        const int wlo = max(0,      (int)ceilf (u - 1.6f));
        const int whi = min(SZ - 1, (int)floorf(u + 1.6f));
        const int hlo = max(0,      (int)ceilf (v - 1.6f));
        const int hhi = min(SZ - 1, (int)floorf(v + 1.6f));

        const int w = wlo + rx;
        const int h = hlo + ry;
        if (w <= whi && h <= hhi) {
            const float ndcy = 1.0f - (2.0f * (float)h + 1.0f) / 128.0f;
            const float ndcx = 1.0f - (2.0f * (float)w + 1.0f) / 128.0f;
            const float dx = ndcx - px;
            const float dy = ndcy - py;
            // mul/mul/add, non-fused: matches reference rounding exactly
            const float d2 =
                __fadd_rn(__fmul_rn(dx, dx), __fmul_rn(dy, dy));
            if (d2 <= R2) {
                // alpha with the reference's exact op sequence
                float dist = __fdiv_rn(d2, R2);
                dist = fminf(fmaxf(dist, 0.001f), 1.0f);
                const float a = 1.0f - __fsqrt_rn(dist);

                const int pix  = ((b * SZ) + h) * SZ + w;
                const int slot = atomicAdd(&d_cnt[pix], 1);
                if (slot < CAPP)
                    d_list[pix * CAPP + slot] =
                        make_float4(pz, a, __int_as_float(p), 0.0f);
            }
        }
    }
}

// ---------------------------------------------------------------- kernel 2
// Block (32,8): 32 pixels (lane = w) x 8 channel-groups (8 ch/thread).
// grid = BN*SZ*(SZ/32) = 1024 blocks, 256 threads each.
__global__ __launch_bounds__(256)
void composite_kernel(float* __restrict__ out)
{
    __shared__ float4 s_list[KN][32];        // [slot][pixel], conflict-free

    const int wt = blockIdx.x & 3;
    const int h  = (blockIdx.x >> 2) & (SZ - 1);
    const int b  = blockIdx.x >> 9;
    const int x  = threadIdx.x;
    const int w  = wt * 32 + x;
    const int cg = threadIdx.y;              // channel group: 8 channels
    const int pix  = ((b * SZ) + h) * SZ + w;
    const int pix0 = ((b * SZ) + h) * SZ + wt * 32;   // block's first pixel

    // counter load + bulk list staging, all issued before the barrier.
    const int cnt_raw = d_cnt[pix];

    // stage slots 0..7 of the block's 32 pixel lists: 256 float4, 1/thread.
    {
        const int j = cg * 32 + x;           // 0..255
        const int p = j >> 3;                // pixel within block
        const int s = j & 7;                 // slot
        s_list[s][p] = d_list[(size_t)(pix0 + p) * CAPP + s];
    }

    // read-before-clear fence (also publishes s_list)
    __syncthreads();
    if (cg == 0) d_cnt[pix] = 0;             // restore all-zero invariant
    const int cnt = min(cnt_raw, CAPP);

    float acc[8];
#pragma unroll
    for (int j = 0; j < 8; ++j) acc[j] = 0.0f;

    const float* sbase = d_srcT + (((size_t)b * PN) << 6) + cg * 8;
    auto gather = [&](int idx, float wi) {
        const float4* s4 = (const float4*)(sbase + ((size_t)idx << 6));
        const float4 v0 = s4[0];
        const float4 v1 = s4[1];
        acc[0] = fmaf(wi, v0.x, acc[0]);
        acc[1] = fmaf(wi, v0.y, acc[1]);
        acc[2] = fmaf(wi, v0.z, acc[2]);
        acc[3] = fmaf(wi, v0.w, acc[3]);
        acc[4] = fmaf(wi, v1.x, acc[4]);
        acc[5] = fmaf(wi, v1.y, acc[5]);
        acc[6] = fmaf(wi, v1.z, acc[6]);
        acc[7] = fmaf(wi, v1.w, acc[7]);
    };

    if (cnt <= KN) {
        // ---- common path: weights from smem, order-independent
        for (int i = 0; i < cnt; ++i) {
            const float4 ei = s_list[i][x];
            float wi = ei.y;                              // a_i
            for (int j = 0; j < cnt; ++j) {
                if (j == i) continue;
                const float4 ej = s_list[j][x];
                if (ej.x < ei.x) wi *= (1.0f - ej.y);
            }
            if (wi > 0.0f) gather(__float_as_int(ei.z), wi);
        }
    } else {
        // ---- cold path (P ~ 1e-7): full global list, top-8 insertion
        const float4* lp = d_list + (size_t)pix * CAPP;
        float zb[KN], ab[KN];
        int   ib[KN];
#pragma unroll
        for (int k = 0; k < KN; ++k) { zb[k] = BIGF; ab[k] = 0.0f; ib[k] = 0; }
        for (int i = 0; i < cnt; ++i) {
            const float4 e = lp[i];
            if (e.x < zb[KN - 1]) {
                float cz = e.x, ca = e.y;
                int   ci = __float_as_int(e.z);
                bool  ins = false;
#pragma unroll
                for (int k = 0; k < KN; ++k) {
                    bool sw = ins | (cz < zb[k]);
                    if (sw) {
                        float tz = zb[k]; zb[k] = cz; cz = tz;
                        float ta = ab[k]; ab[k] = ca; ca = ta;
                        int   ti = ib[k]; ib[k] = ci; ci = ti;
                        ins = true;
                    }
                }
            }
        }
        float T = 1.0f;
#pragma unroll
        for (int k = 0; k < KN; ++k) {
            if (zb[k] < BIGF) {
                const float wi = ab[k] * T;
                T = T * (1.0f - ab[k]);
                if (wi > 0.0f) gather(ib[k], wi);
            }
        }
    }

    // out[b,c,h,w]; lane = w -> coalesced 128B stores per channel plane
    float* ob = out + (((size_t)(b * CN + cg * 8)) * SZ + h) * SZ + w;
#pragma unroll
    for (int j = 0; j < 8; ++j)
        ob[(size_t)j * SZ * SZ] = acc[j];
}

// ---------------------------------------------------------------- launch
extern "C" void kernel_launch(void* const* d_in, const int* in_sizes, int n_in,
                              void* d_out, int out_size)
{
    const float* pts = (const float*)d_in[0];  // [B,P,3]
    const float* src = (const float*)d_in[1];  // [B,C,P]
    float* out = (float*)d_out;                // [B,C,H,W]

    prep_kernel<<<TRB + SCB, 256>>>(src, pts);
    composite_kernel<<<BN * SZ * (SZ / 32), dim3(32, 8)>>>(out);
}

// round 16
// speedup vs baseline: 1.1561x; 1.1561x over previous
#include <cuda_runtime.h>

// RasterizePointsXYsBlending — flat scatter + smem-staged composite + PDL.
// B=2, P=2048, C=64, SIZE=128, K=8, RADIUS=1.5px, RAD_POW=2, TAU=1.
//
//  K1 prep (384 blocks x 256 thr):  [R12/R14-verbatim]
//     blocks [0,128):  transpose src [B,C,P] -> srcT [B,P,C]; 2 tiles per
//                      block, 2 independent LDG.128 per thread (MLP=8).
//     blocks [128,384): scatter — one thread per (point, 4x4 bbox cell):
//                      <=1 exact inside-test, <=1 atomic append (depth-1 chain).
//  K2 composite (1024 blocks x (32,4)) — R14-verbatim, launched with
//     PROGRAMMATIC DEPENDENT LAUNCH: blocks come resident during prep and
//     cudaGridDependencySynchronize() gates the first read of prep's
//     outputs — launch gap and ramp overlap prep execution.

#define BN 2
#define PN 2048
#define CN 64
#define SZ 128
#define KN 8
#define BIGF 1e10f
// r_ndc = 1.5/128*2 = 3*2^-7 ; r2 = 9*2^-14 (exact fp32)
#define R2 0.00054931640625f

#define CAPP 16                       // per-pixel list capacity (mean ~0.9)
#define NPIX (BN * SZ * SZ)           // 32768
#define TRB 128                       // transpose blocks (2 tiles each)
#define SCB 256                       // scatter blocks (256*256 = BN*PN*16)

__device__ float  d_srcT[BN * PN * CN];   // src transposed to [b,p,c]
__device__ int    d_cnt[NPIX];            // per-pixel counts (invariant: 0)
__device__ float4 d_list[NPIX * CAPP];    // (z, alpha, bitcast idx, -)

// ---------------------------------------------------------------- kernel 1
__global__ __launch_bounds__(256)
void prep_kernel(const float* __restrict__ src, const float* __restrict__ pts)
{
    if (blockIdx.x < TRB) {
        // -------- transpose: 2 tiles/block, 2 independent LDG.128/thread --
        __shared__ float t[2][32][33];
        const int i  = threadIdx.x;
        const int y  = i >> 3;            // 0..31 (channel row in tile)
        const int xq = (i & 7) * 4;       // 0,4,...,28 (p quad)

        float4 v[2];
#pragma unroll
        for (int q = 0; q < 2; ++q) {
            const int tl = blockIdx.x + q * TRB;     // covers 256 tiles
            const int b  = tl >> 7;
            const int c0 = ((tl >> 6) & 1) * 32;
            const int p0 = (tl & 63) * 32;
            v[q] = *(const float4*)
                (src + ((size_t)(b * CN + c0 + y) << 11) + p0 + xq);
        }
#pragma unroll
        for (int q = 0; q < 2; ++q) {
            t[q][y][xq + 0] = v[q].x;
            t[q][y][xq + 1] = v[q].y;
            t[q][y][xq + 2] = v[q].z;
            t[q][y][xq + 3] = v[q].w;
        }
        __syncthreads();

        const int c  = i & 31;            // output lane = channel
        const int pq = i >> 5;            // 0..7 (p row group of 4)
#pragma unroll
        for (int q = 0; q < 2; ++q) {
            const int tl = blockIdx.x + q * TRB;
            const int b  = tl >> 7;
            const int c0 = ((tl >> 6) & 1) * 32;
            const int p0 = (tl & 63) * 32;
#pragma unroll
            for (int r = 0; r < 4; ++r) {
                const int p = pq * 4 + r;
                d_srcT[((size_t)(b * PN + p0 + p) << 6) + c0 + c] =
                    t[q][c][p];
            }
        }
    } else {
        // ------- scatter: one thread per (point, 4x4 bbox cell) ----------
        const int s = (blockIdx.x - TRB) * 256 + threadIdx.x;
        const int cell = s & 15;
        const int rx   = cell & 3;
        const int ry   = cell >> 2;
        const int gp   = s >> 4;               // global point id
        const int b    = gp >> 11;
        const int p    = gp & (PN - 1);

        const float px = -pts[gp * 3 + 0];     // sign flip from forward
        const float py = -pts[gp * 3 + 1];
        const float pz =  pts[gp * 3 + 2];

        // pixel coords of the point: ndc(i) = 1-(2i+1)/128
        const float u = (1.0f - px) * 64.0f - 0.5f;   // w
        const float v = (1.0f - py) * 64.0f - 0.5f;   // h

        // radius 1.5 px + fp margin; bbox spans <=4 cells per axis
        const int wlo = max(0,      (int)ceilf (u - 1.6f));
        const int whi = min(SZ - 1, (int)floorf(u + 1.6f));
        const int hlo = max(0,      (int)ceilf (v - 1.6f));
        const int hhi = min(SZ - 1, (int)floorf(v + 1.6f));

        const int w = wlo + rx;
        const int h = hlo + ry;
        if (w <= whi && h <= hhi) {
            const float ndcy = 1.0f - (2.0f * (float)h + 1.0f) / 128.0f;
            const float ndcx = 1.0f - (2.0f * (float)w + 1.0f) / 128.0f;
            const float dx = ndcx - px;
            const float dy = ndcy - py;
            // mul/mul/add, non-fused: matches reference rounding exactly
            const float d2 =
                __fadd_rn(__fmul_rn(dx, dx), __fmul_rn(dy, dy));
            if (d2 <= R2) {
                // alpha with the reference's exact op sequence
                float dist = __fdiv_rn(d2, R2);
                dist = fminf(fmaxf(dist, 0.001f), 1.0f);
                const float a = 1.0f - __fsqrt_rn(dist);

                const int pix  = ((b * SZ) + h) * SZ + w;
                const int slot = atomicAdd(&d_cnt[pix], 1);
                if (slot < CAPP)
                    d_list[pix * CAPP + slot] =
                        make_float4(pz, a, __int_as_float(p), 0.0f);
            }
        }
    }
}

// ---------------------------------------------------------------- kernel 2
// Block (32,4): 32 pixels (lane = w) x 4 channel-groups (16 ch/thread).
// grid = BN*SZ*(SZ/32) = 1024 blocks. Launched with PDL.
__global__ __launch_bounds__(128)
void composite_kernel(float* __restrict__ out)
{
    __shared__ float4 s_list[KN][32];        // [slot][pixel], conflict-free

    const int wt = blockIdx.x & 3;
    const int h  = (blockIdx.x >> 2) & (SZ - 1);
    const int b  = blockIdx.x >> 9;
    const int x  = threadIdx.x;
    const int w  = wt * 32 + x;
    const int cg = threadIdx.y;              // channel group: 16 channels
    const int pix  = ((b * SZ) + h) * SZ + w;
    const int pix0 = ((b * SZ) + h) * SZ + wt * 32;   // block's first pixel

    // PDL: blocks are resident during prep; wait for prep's writes before
    // touching d_cnt / d_list / d_srcT.
#if __CUDA_ARCH__ >= 900
    cudaGridDependencySynchronize();
#endif

    // counter load + bulk list staging, all issued before the barrier.
    const int cnt_raw = d_cnt[pix];

    // stage slots 0..7 of the block's 32 pixel lists: 256 float4, 2/thread.
    const int tid = cg * 32 + x;             // 0..127
#pragma unroll
    for (int q = 0; q < 2; ++q) {
        const int j = tid * 2 + q;           // 0..255
        const int p = j >> 3;                // pixel within block
        const int s = j & 7;                 // slot
        s_list[s][p] = d_list[(size_t)(pix0 + p) * CAPP + s];
    }

    // read-before-clear fence (also publishes s_list)
    __syncthreads();
    if (cg == 0) d_cnt[pix] = 0;             // restore all-zero invariant
    const int cnt = min(cnt_raw, CAPP);

    float acc[16];
#pragma unroll
    for (int j = 0; j < 16; ++j) acc[j] = 0.0f;

    const float* sbase = d_srcT + (((size_t)b * PN) << 6) + cg * 16;
    auto gather = [&](int idx, float wi) {
        const float4* s4 = (const float4*)(sbase + ((size_t)idx << 6));
#pragma unroll
        for (int q = 0; q < 4; ++q) {
            const float4 v = s4[q];
            acc[4 * q + 0] = fmaf(wi, v.x, acc[4 * q + 0]);
            acc[4 * q + 1] = fmaf(wi, v.y, acc[4 * q + 1]);
            acc[4 * q + 2] = fmaf(wi, v.z, acc[4 * q + 2]);
            acc[4 * q + 3] = fmaf(wi, v.w, acc[4 * q + 3]);
        }
    };

    if (cnt <= KN) {
        // ---- common path: weights from smem, order-independent
        for (int i = 0; i < cnt; ++i) {
            const float4 ei = s_list[i][x];
            float wi = ei.y;                              // a_i
            for (int j = 0; j < cnt; ++j) {
                if (j == i) continue;
                const float4 ej = s_list[j][x];
                if (ej.x < ei.x) wi *= (1.0f - ej.y);
            }
            if (wi > 0.0f) gather(__float_as_int(ei.z), wi);
        }
    } else {
        // ---- cold path (P ~ 1e-7): full global list, top-8 insertion
        const float4* lp = d_list + (size_t)pix * CAPP;
        float zb[KN], ab[KN];
        int   ib[KN];
#pragma unroll
        for (int k = 0; k < KN; ++k) { zb[k] = BIGF; ab[k] = 0.0f; ib[k] = 0; }
        for (int i = 0; i < cnt; ++i) {
            const float4 e = lp[i];
            if (e.x < zb[KN - 1]) {
                float cz = e.x, ca = e.y;
                int   ci = __float_as_int(e.z);
                bool  ins = false;
#pragma unroll
                for (int k = 0; k < KN; ++k) {
                    bool sw = ins | (cz < zb[k]);
                    if (sw) {
                        float tz = zb[k]; zb[k] = cz; cz = tz;
                        float ta = ab[k]; ab[k] = ca; ca = ta;
                        int   ti = ib[k]; ib[k] = ci; ci = ti;
                        ins = true;
                    }
                }
            }
        }
        float T = 1.0f;
#pragma unroll
        for (int k = 0; k < KN; ++k) {
            if (zb[k] < BIGF) {
                const float wi = ab[k] * T;
                T = T * (1.0f - ab[k]);
                if (wi > 0.0f) gather(ib[k], wi);
            }
        }
    }

    // out[b,c,h,w]; lane = w -> coalesced 128B stores per channel plane
    float* ob = out + (((size_t)(b * CN + cg * 16)) * SZ + h) * SZ + w;
#pragma unroll
    for (int j = 0; j < 16; ++j)
        ob[(size_t)j * SZ * SZ] = acc[j];
}

// ---------------------------------------------------------------- launch
extern "C" void kernel_launch(void* const* d_in, const int* in_sizes, int n_in,
                              void* d_out, int out_size)
{
    const float* pts = (const float*)d_in[0];  // [B,P,3]
    const float* src = (const float*)d_in[1];  // [B,C,P]
    float* out = (float*)d_out;                // [B,C,H,W]

    prep_kernel<<<TRB + SCB, 256>>>(src, pts);

    // composite with Programmatic Dependent Launch: blocks go resident
    // during prep; cudaGridDependencySynchronize() inside gates the reads.
    cudaLaunchConfig_t cfg = {};
    cfg.gridDim  = dim3(BN * SZ * (SZ / 32));
    cfg.blockDim = dim3(32, 4);
    cudaLaunchAttribute attr[1];
    attr[0].id = cudaLaunchAttributeProgrammaticStreamSerialization;
    attr[0].val.programmaticStreamSerializationAllowed = 1;
    cfg.attrs = attr;
    cfg.numAttrs = 1;
    cudaLaunchKernelEx(&cfg, composite_kernel, (float*)d_out);
}